// round 11
// baseline (speedup 1.0000x reference)
#include <cuda_runtime.h>

#define N_NODES 100000
#define N_EDGES 1600000
#define D 64
#define HID 256
#define OUTD 64
#define MB 128           // nodes per MLP CTA
#define BN_EPS 1e-5f
#define NBLK 391         // ceil(N_NODES/256)

// ---- device scratch (no allocations allowed; zero-initialized at load) ----
__device__ float g_agg[N_NODES * D];
__device__ int   g_cnt[N_NODES];              // in-degree (re-zeroed by k_mlp)
__device__ int   g_off[N_NODES];              // CSR offsets
__device__ int   g_pos[N_NODES];              // fill cursors
__device__ unsigned long long g_desc[NBLK];   // scan descriptors (re-zeroed by k_count)
__device__ int   g_csr[N_EDGES];              // src ids grouped by dst
__device__ float g_y[N_NODES * OUTD];
__device__ float g_stats[2 * OUTD];           // re-zeroed by k_mlp last CTA
__device__ float g_scale[OUTD];
__device__ float g_shift[OUTD];
__device__ unsigned g_done;                   // re-zeroed by k_mlp last CTA

// -------------------------------------------------------------------
__global__ void k_count(const int* __restrict__ dst) {
    int e = blockIdx.x * blockDim.x + threadIdx.x;
    if (e < NBLK) g_desc[e] = 0ULL;
    if (e < N_EDGES) atomicAdd(&g_cnt[__ldg(dst + e)], 1);
}

// -------------------------------------------------------------------
// Single-pass exclusive scan (decoupled lookback); 391 CTAs co-resident.
// -------------------------------------------------------------------
__global__ void k_scan() {
    __shared__ int s[256];
    __shared__ int s_excl;
    int b = blockIdx.x, t = threadIdx.x, i = b * 256 + t;
    int v = (i < N_NODES) ? g_cnt[i] : 0;
    s[t] = v; __syncthreads();
    #pragma unroll
    for (int off = 1; off < 256; off <<= 1) {
        int x = (t >= off) ? s[t - off] : 0;
        __syncthreads();
        s[t] += x;
        __syncthreads();
    }
    int total = s[255];
    if (t == 0) {
        unsigned long long flag = (b == 0) ? 2ULL : 1ULL;
        atomicExch(&g_desc[b], (flag << 62) | (unsigned)total);
        int excl = 0;
        if (b > 0) {
            int ib = b - 1;
            while (true) {
                unsigned long long d;
                do { d = atomicAdd(&g_desc[ib], 0ULL); } while ((d >> 62) == 0ULL);
                excl += (int)(d & 0xffffffffULL);
                if ((d >> 62) == 2ULL) break;
                ib--;
            }
            atomicExch(&g_desc[b], (2ULL << 62) | (unsigned)(excl + total));
        }
        s_excl = excl;
    }
    __syncthreads();
    if (i < N_NODES) {
        int o = s_excl + s[t] - v;
        g_off[i] = o;
        g_pos[i] = o;
    }
}

// -------------------------------------------------------------------
__global__ void k_fill(const int* __restrict__ src, const int* __restrict__ dst) {
    int e = blockIdx.x * blockDim.x + threadIdx.x;
    if (e < N_EDGES) {
        int d = __ldg(dst + e);
        int p = atomicAdd(&g_pos[d], 1);
        g_csr[p] = __ldg(src + e);
    }
}

// -------------------------------------------------------------------
// Atomic-free gather: one warp per node; 8 independent row reads in flight.
// (Measured ~35us at occ ~81%.)
// -------------------------------------------------------------------
__global__ void k_gather(const float* __restrict__ h) {
    int w = (blockIdx.x * blockDim.x + threadIdx.x) >> 5;
    if (w >= N_NODES) return;
    int lane = threadIdx.x & 31;
    int beg = g_off[w], cnt = g_cnt[w];
    float ax = 0.f, ay = 0.f;
    int j = 0;
    for (; j + 8 <= cnt; j += 8) {
        int sidx[8];
        #pragma unroll
        for (int u = 0; u < 8; u++) sidx[u] = __ldg(g_csr + beg + j + u);
        #pragma unroll
        for (int u = 0; u < 8; u++) {
            float2 v = *(const float2*)(h + (size_t)sidx[u] * D + lane * 2);
            ax += v.x; ay += v.y;
        }
    }
    for (; j < cnt; j++) {
        int s0 = __ldg(g_csr + beg + j);
        float2 v = *(const float2*)(h + (size_t)s0 * D + lane * 2);
        ax += v.x; ay += v.y;
    }
    *(float2*)(g_agg + (size_t)w * D + lane * 2) = make_float2(ax, ay);
}

// -------------------------------------------------------------------
// tf32 mma helpers
// -------------------------------------------------------------------
__device__ __forceinline__ unsigned f2t(float f) {
    unsigned u;
    asm("cvt.rna.tf32.f32 %0, %1;" : "=r"(u) : "f"(f));
    return u;
}
__device__ __forceinline__ void mma8(float* c, const unsigned* a, const unsigned* b) {
    asm volatile(
        "mma.sync.aligned.m16n8k8.row.col.f32.tf32.tf32.f32 "
        "{%0,%1,%2,%3},{%4,%5,%6,%7},{%8,%9},{%0,%1,%2,%3};"
        : "+f"(c[0]), "+f"(c[1]), "+f"(c[2]), "+f"(c[3])
        : "r"(a[0]), "r"(a[1]), "r"(a[2]), "r"(a[3]), "r"(b[0]), "r"(b[1]));
}

// -------------------------------------------------------------------
// Fused MLP (tf32 m16n8k8), 512 threads / 16 warps per CTA.
// Register-lean: phase A runs 2 passes of 8 accumulator tiles (32 regs)
// instead of 16 (64 regs) => no spills under the 128-reg cap.
// B-fragments for adjacent n-tile pairs share one uint4 LDS.128.
// W-pair layout: word = (tile&1)*2 + hk at ((ks*TP + tile>>1)*32+lane)*4.
// -------------------------------------------------------------------
__global__ __launch_bounds__(512, 1)
void k_mlp(const float* __restrict__ h,
           const float* __restrict__ W1, const float* __restrict__ b1,
           const float* __restrict__ W2, const float* __restrict__ b2,
           const float* __restrict__ gamma, const float* __restrict__ beta) {
    extern __shared__ unsigned smu[];
    unsigned* sXp = smu;                    // 8192 words
    unsigned* sHp = smu + 8192;             // 32768 words
    unsigned* sWp = smu + 8192 + 32768;     // 16384 words
    float* sInv = (float*)(smu + 57344);    // 128 words
    float* sS = (float*)smu;                // stats reuse (phase B)
    __shared__ int s_last;

    int t = threadIdx.x;
    int lane = t & 31, w = t >> 5;
    int g = lane >> 2, tg = lane & 3;
    int nb = blockIdx.x * MB;

    // --- per-row 1/deg, consume + zero g_cnt ---
    if (t < MB) {
        int gn = nb + t;
        float invd = 0.f;
        if (gn < N_NODES) {
            float dg = (float)g_cnt[gn];
            invd = 1.f / fmaxf(dg, 1.f);
            g_cnt[gn] = 0;
        }
        sInv[t] = invd;
    }
    __syncthreads();

    // --- X permute-load: x = agg * invdeg + h ---
    #pragma unroll
    for (int i = 0; i < (MB * D) / 512; i++) {
        int idx = i * 512 + t;
        int row = idx >> 6, k = idx & 63;
        int gn = nb + row;
        float x = 0.f;
        if (gn < N_NODES)
            x = g_agg[(size_t)gn * D + k] * sInv[row] + h[(size_t)gn * D + k];
        int rowg = row >> 4, r = row & 15, gg = r & 7, hr = r >> 3;
        int ks = k >> 3, kr = k & 7, tt = kr & 3, hk = kr >> 2;
        sXp[((rowg * 8 + ks) * 32 + gg * 4 + tt) * 4 + hr + 2 * hk] = f2t(x);
    }
    // --- W1 permute-load [64][256], tile-PAIRED b-frags ---
    #pragma unroll
    for (int i = 0; i < (D * HID) / 512; i++) {
        int idx = i * 512 + t;
        int k = idx >> 8, n = idx & 255;
        int ks = k >> 3, kr = k & 7, tt = kr & 3, hk = kr >> 2;
        int tile = n >> 3, gg = n & 7;
        sWp[((ks * 16 + (tile >> 1)) * 32 + gg * 4 + tt) * 4 + (tile & 1) * 2 + hk]
            = f2t(W1[idx]);
    }
    __syncthreads();

    // --- Phase A: H = relu(X @ W1 + b1); 2 passes x 8 tiles per warp ---
    {
        int rowg = w & 7, ch = w >> 3;   // ch in {0,1}: warp covers 32 of 256 cols
        #pragma unroll
        for (int pass = 0; pass < 2; pass++) {
            float acc[8][4];
            #pragma unroll
            for (int tt = 0; tt < 8; tt++) {
                int n0 = (ch * 16 + pass * 8 + tt) * 8;
                float v0 = __ldg(b1 + n0 + 2 * tg), v1 = __ldg(b1 + n0 + 2 * tg + 1);
                acc[tt][0] = v0; acc[tt][1] = v1; acc[tt][2] = v0; acc[tt][3] = v1;
            }
            #pragma unroll
            for (int ks = 0; ks < 8; ks++) {
                unsigned a[4];
                *(uint4*)a = *(const uint4*)&sXp[((rowg * 8 + ks) * 32 + lane) * 4];
                #pragma unroll
                for (int tp = 0; tp < 4; tp++) {
                    unsigned bb[4];
                    *(uint4*)bb = *(const uint4*)
                        &sWp[((ks * 16 + ch * 8 + pass * 4 + tp) * 32 + lane) * 4];
                    mma8(acc[2 * tp],     a, bb);
                    mma8(acc[2 * tp + 1], a, bb + 2);
                }
            }
            #pragma unroll
            for (int tt = 0; tt < 8; tt++) {
                int n0 = (ch * 16 + pass * 8 + tt) * 8;
                #pragma unroll
                for (int cr = 0; cr < 4; cr++) {
                    int col = n0 + 2 * tg + (cr & 1);
                    int kB = col >> 3, krB = col & 7, tgB = krB & 3, hkB = krB >> 2;
                    sHp[((rowg * 32 + kB) * 32 + g * 4 + tgB) * 4 + (cr >> 1) + 2 * hkB]
                        = f2t(fmaxf(acc[tt][cr], 0.f));
                }
            }
        }
    }
    __syncthreads();

    // --- zero stats partials, W2 permute-load [256][64], tile-PAIRED ---
    if (t < 128) sS[t] = 0.f;
    #pragma unroll
    for (int i = 0; i < (HID * OUTD) / 512; i++) {
        int idx = i * 512 + t;
        int j = idx >> 6, o = idx & 63;
        int ks = j >> 3, kr = j & 7, tt = kr & 3, hk = kr >> 2;
        int tile = o >> 3, gg = o & 7;
        sWp[((ks * 4 + (tile >> 1)) * 32 + gg * 4 + tt) * 4 + (tile & 1) * 2 + hk]
            = f2t(W2[idx]);
    }
    __syncthreads();

    // --- Phase B: y = relu(H @ W2 + b2), write y + BN partials ---
    {
        int rowg = w & 7, ch = w >> 3;   // ch in {0,1}: 4 n-tiles each
        float acc[4][4];
        #pragma unroll
        for (int tt = 0; tt < 4; tt++) {
            int o0 = (ch * 4 + tt) * 8;
            float v0 = __ldg(b2 + o0 + 2 * tg), v1 = __ldg(b2 + o0 + 2 * tg + 1);
            acc[tt][0] = v0; acc[tt][1] = v1; acc[tt][2] = v0; acc[tt][3] = v1;
        }
        #pragma unroll
        for (int ks = 0; ks < 32; ks++) {
            unsigned a[4];
            *(uint4*)a = *(const uint4*)&sHp[((rowg * 32 + ks) * 32 + lane) * 4];
            #pragma unroll
            for (int tp = 0; tp < 2; tp++) {
                unsigned bb[4];
                *(uint4*)bb = *(const uint4*)
                    &sWp[((ks * 4 + ch * 2 + tp) * 32 + lane) * 4];
                mma8(acc[2 * tp],     a, bb);
                mma8(acc[2 * tp + 1], a, bb + 2);
            }
        }
        float ps[8] = {0,0,0,0,0,0,0,0}, pq[8] = {0,0,0,0,0,0,0,0};
        #pragma unroll
        for (int tt = 0; tt < 4; tt++) {
            #pragma unroll
            for (int cr = 0; cr < 4; cr++) {
                int row = nb + rowg * 16 + g + (cr >> 1) * 8;
                int col = (ch * 4 + tt) * 8 + 2 * tg + (cr & 1);
                float y = fmaxf(acc[tt][cr], 0.f);
                if (row < N_NODES) {
                    g_y[(size_t)row * OUTD + col] = y;
                    ps[tt * 2 + (cr & 1)] += y;
                    pq[tt * 2 + (cr & 1)] += y * y;
                }
            }
        }
        #pragma unroll
        for (int i = 0; i < 8; i++) {
            int col = (ch * 4 + (i >> 1)) * 8 + 2 * tg + (i & 1);
            atomicAdd(&sS[col], ps[i]);
            atomicAdd(&sS[64 + col], pq[i]);
        }
    }
    __syncthreads();
    if (t < 128) {
        atomicAdd(&g_stats[t], sS[t]);
        __threadfence();
    }
    __syncthreads();
    if (t == 0)
        s_last = (atomicAdd(&g_done, 1u) == (unsigned)(gridDim.x - 1)) ? 1 : 0;
    __syncthreads();
    if (s_last) {
        __threadfence();
        if (t < OUTD) {
            float s0 = atomicAdd(&g_stats[t], 0.f);
            float q  = atomicAdd(&g_stats[OUTD + t], 0.f);
            float mean = s0 * (1.0f / N_NODES);
            float var = q * (1.0f / N_NODES) - mean * mean;
            float sc = gamma[t] * rsqrtf(var + BN_EPS);
            g_scale[t] = sc;
            g_shift[t] = beta[t] - mean * sc;
        }
        __syncthreads();
        if (t < 2 * OUTD) g_stats[t] = 0.f;
        if (t == 0) g_done = 0;
    }
}

// -------------------------------------------------------------------
__global__ void k_apply(float* __restrict__ out) {
    int i = blockIdx.x * blockDim.x + threadIdx.x;
    if (i >= N_NODES * OUTD / 4) return;
    int o4 = (i & (OUTD / 4 - 1)) * 4;
    float4 y = ((const float4*)g_y)[i];
    float4 r;
    r.x = y.x * g_scale[o4 + 0] + g_shift[o4 + 0];
    r.y = y.y * g_scale[o4 + 1] + g_shift[o4 + 1];
    r.z = y.z * g_scale[o4 + 2] + g_shift[o4 + 2];
    r.w = y.w * g_scale[o4 + 3] + g_shift[o4 + 3];
    ((float4*)out)[i] = r;
}

// -------------------------------------------------------------------
extern "C" void kernel_launch(void* const* d_in, const int* in_sizes, int n_in,
                              void* d_out, int out_size) {
    const float* h     = (const float*)d_in[0];
    const float* W1    = (const float*)d_in[1];
    const float* b1    = (const float*)d_in[2];
    const float* W2    = (const float*)d_in[3];
    const float* b2    = (const float*)d_in[4];
    const float* gamma = (const float*)d_in[5];
    const float* beta  = (const float*)d_in[6];
    const int*   src   = (const int*)d_in[7];
    const int*   dst   = (const int*)d_in[8];
    float* out = (float*)d_out;

    const int smem_bytes = (8192 + 32768 + 16384 + 128) * 4;  // 229888
    cudaFuncSetAttribute(k_mlp, cudaFuncAttributeMaxDynamicSharedMemorySize, smem_bytes);

    k_count<<<N_EDGES / 256, 256>>>(dst);
    k_scan<<<NBLK, 256>>>();
    k_fill<<<N_EDGES / 256, 256>>>(src, dst);
    k_gather<<<(N_NODES * 32 + 255) / 256, 256>>>(h);
    k_mlp<<<(N_NODES + MB - 1) / MB, 512, smem_bytes>>>(h, W1, b1, W2, b2, gamma, beta);
    k_apply<<<(N_NODES * OUTD / 4 + 255) / 256, 256>>>(out);
}

// round 12
// speedup vs baseline: 1.1776x; 1.1776x over previous
#include <cuda_runtime.h>
#include <cuda_fp16.h>

#define N_NODES 100000
#define N_EDGES 1600000
#define D 64
#define HID 256
#define OUTD 64
#define MB 128           // nodes per MLP CTA
#define BN_EPS 1e-5f
#define NBLK 391         // ceil(N_NODES/256)

// ---- device scratch (no allocations allowed; zero-initialized at load) ----
__device__ float g_agg[N_NODES * D];
__device__ int   g_cnt[N_NODES];              // in-degree (re-zeroed by k_mlp)
__device__ int   g_off[N_NODES];              // CSR offsets
__device__ int   g_pos[N_NODES];              // fill cursors
__device__ unsigned long long g_desc[NBLK];   // scan descriptors (re-zeroed by k_count)
__device__ int   g_csr[N_EDGES];              // src ids grouped by dst
__device__ float g_y[N_NODES * OUTD];
__device__ float g_stats[2 * OUTD];           // re-zeroed by k_mlp last CTA
__device__ float g_scale[OUTD];
__device__ float g_shift[OUTD];
__device__ unsigned g_done;                   // re-zeroed by k_mlp last CTA

// -------------------------------------------------------------------
__global__ void k_count(const int* __restrict__ dst) {
    int e = blockIdx.x * blockDim.x + threadIdx.x;
    if (e < NBLK) g_desc[e] = 0ULL;
    if (e < N_EDGES) atomicAdd(&g_cnt[__ldg(dst + e)], 1);
}

// -------------------------------------------------------------------
// Single-pass exclusive scan (decoupled lookback); 391 CTAs co-resident.
// -------------------------------------------------------------------
__global__ void k_scan() {
    __shared__ int s[256];
    __shared__ int s_excl;
    int b = blockIdx.x, t = threadIdx.x, i = b * 256 + t;
    int v = (i < N_NODES) ? g_cnt[i] : 0;
    s[t] = v; __syncthreads();
    #pragma unroll
    for (int off = 1; off < 256; off <<= 1) {
        int x = (t >= off) ? s[t - off] : 0;
        __syncthreads();
        s[t] += x;
        __syncthreads();
    }
    int total = s[255];
    if (t == 0) {
        unsigned long long flag = (b == 0) ? 2ULL : 1ULL;
        atomicExch(&g_desc[b], (flag << 62) | (unsigned)total);
        int excl = 0;
        if (b > 0) {
            int ib = b - 1;
            while (true) {
                unsigned long long d;
                do { d = atomicAdd(&g_desc[ib], 0ULL); } while ((d >> 62) == 0ULL);
                excl += (int)(d & 0xffffffffULL);
                if ((d >> 62) == 2ULL) break;
                ib--;
            }
            atomicExch(&g_desc[b], (2ULL << 62) | (unsigned)(excl + total));
        }
        s_excl = excl;
    }
    __syncthreads();
    if (i < N_NODES) {
        int o = s_excl + s[t] - v;
        g_off[i] = o;
        g_pos[i] = o;
    }
}

// -------------------------------------------------------------------
__global__ void k_fill(const int* __restrict__ src, const int* __restrict__ dst) {
    int e = blockIdx.x * blockDim.x + threadIdx.x;
    if (e < N_EDGES) {
        int d = __ldg(dst + e);
        int p = atomicAdd(&g_pos[d], 1);
        g_csr[p] = __ldg(src + e);
    }
}

// -------------------------------------------------------------------
// Atomic-free gather: one warp per node; 8 independent row reads in flight.
// -------------------------------------------------------------------
__global__ void k_gather(const float* __restrict__ h) {
    int w = (blockIdx.x * blockDim.x + threadIdx.x) >> 5;
    if (w >= N_NODES) return;
    int lane = threadIdx.x & 31;
    int beg = g_off[w], cnt = g_cnt[w];
    float ax = 0.f, ay = 0.f;
    int j = 0;
    for (; j + 8 <= cnt; j += 8) {
        int sidx[8];
        #pragma unroll
        for (int u = 0; u < 8; u++) sidx[u] = __ldg(g_csr + beg + j + u);
        #pragma unroll
        for (int u = 0; u < 8; u++) {
            float2 v = *(const float2*)(h + (size_t)sidx[u] * D + lane * 2);
            ax += v.x; ay += v.y;
        }
    }
    for (; j < cnt; j++) {
        int s0 = __ldg(g_csr + beg + j);
        float2 v = *(const float2*)(h + (size_t)s0 * D + lane * 2);
        ax += v.x; ay += v.y;
    }
    *(float2*)(g_agg + (size_t)w * D + lane * 2) = make_float2(ax, ay);
}

// -------------------------------------------------------------------
// fp16 mma helpers (m16n8k16, fp32 accumulate)
// -------------------------------------------------------------------
__device__ __forceinline__ unsigned pack2(float a, float b) {
    __half2 hh = __halves2half2(__float2half_rn(a), __float2half_rn(b));
    return *(unsigned*)&hh;
}
__device__ __forceinline__ void mma16(float* c, const unsigned* a, const unsigned* b) {
    asm volatile(
        "mma.sync.aligned.m16n8k16.row.col.f32.f16.f16.f32 "
        "{%0,%1,%2,%3},{%4,%5,%6,%7},{%8,%9},{%0,%1,%2,%3};"
        : "+f"(c[0]), "+f"(c[1]), "+f"(c[2]), "+f"(c[3])
        : "r"(a[0]), "r"(a[1]), "r"(a[2]), "r"(a[3]), "r"(b[0]), "r"(b[1]));
}

// -------------------------------------------------------------------
// Fused MLP (fp16 m16n8k16), 512 threads / 16 warps per CTA.
// All smem in fragment-permuted packed-half2 layouts:
//   sXp: [rowg8][kstep4][lane32][4]           (16 KB)  A-frags of X (K=64)
//   sHp: [rowg8][kstep16][lane32][4]          (64 KB)  A-frags of H (K=256)
//   sWp: W1 [ks4][tp16][lane32][4] / W2 [ks16][tp4][lane32][4]  (32 KB)
// m16n8k16 maps (lane l: g=l>>2, tg=l&3):
//   A reg r = hr + 2*hk : hr=rowhalf(row&15>=8), hk=(k&15)>>3; halves = k&1
//   B reg r = (k&15)>>3 ; b covers k rows 2tg,2tg+1(+8), col n0+g
//   C: c0=(g,2tg) c1=(g,2tg+1) c2=(g+8,2tg) c3=(g+8,2tg+1)
// -------------------------------------------------------------------
__global__ __launch_bounds__(512, 1)
void k_mlp(const float* __restrict__ h,
           const float* __restrict__ W1, const float* __restrict__ b1,
           const float* __restrict__ W2, const float* __restrict__ b2,
           const float* __restrict__ gamma, const float* __restrict__ beta) {
    extern __shared__ unsigned smu[];
    unsigned* sXp = smu;                    // 4096 words
    unsigned* sHp = smu + 4096;             // 16384 words
    unsigned* sWp = smu + 4096 + 16384;     // 8192 words
    float* sS = (float*)smu;                // stats reuse (phase B; sXp dead then)
    __shared__ float sInv[MB];
    __shared__ int s_last;

    int t = threadIdx.x;
    int lane = t & 31, w = t >> 5;
    int g = lane >> 2, tg = lane & 3;
    int nb = blockIdx.x * MB;

    // --- per-row 1/deg, consume + zero g_cnt ---
    if (t < MB) {
        int gn = nb + t;
        float invd = 0.f;
        if (gn < N_NODES) {
            float dg = (float)g_cnt[gn];
            invd = 1.f / fmaxf(dg, 1.f);
            g_cnt[gn] = 0;
        }
        sInv[t] = invd;
    }
    __syncthreads();

    // --- X permute-load (packed pairs): x = agg*invdeg + h ---
    #pragma unroll
    for (int i = 0; i < (MB * D / 2) / 512; i++) {   // 8 iters
        int idx = i * 512 + t;
        int row = idx >> 5, kp = idx & 31, k0 = kp * 2;
        int gn = nb + row;
        float x0 = 0.f, x1 = 0.f;
        if (gn < N_NODES) {
            float2 av = *(const float2*)(g_agg + (size_t)gn * D + k0);
            float2 hv = *(const float2*)(h + (size_t)gn * D + k0);
            float iv = sInv[row];
            x0 = av.x * iv + hv.x;
            x1 = av.y * iv + hv.y;
        }
        int rowg = row >> 4, r = row & 15, gg = r & 7, hr = r >> 3;
        int kstep = k0 >> 4, kk = k0 & 15, tt = (kk & 7) >> 1, hk = kk >> 3;
        sXp[((rowg * 4 + kstep) * 32 + gg * 4 + tt) * 4 + hr + 2 * hk] = pack2(x0, x1);
    }
    // --- W1 permute-load [64][256] (pack along k, tile-paired) ---
    #pragma unroll
    for (int i = 0; i < (D / 2 * HID) / 512; i++) {  // 16 iters
        int idx = i * 512 + t;
        int kp = idx >> 8, n = idx & 255, k0 = kp * 2;
        float w0 = W1[k0 * HID + n], w1 = W1[(k0 + 1) * HID + n];
        int kstep = k0 >> 4, kk = k0 & 15, tt = (kk & 7) >> 1, breg = kk >> 3;
        int tile = n >> 3, gg = n & 7;
        sWp[((kstep * 16 + (tile >> 1)) * 32 + gg * 4 + tt) * 4 + (tile & 1) * 2 + breg]
            = pack2(w0, w1);
    }
    __syncthreads();

    // --- Phase A: H = relu(X @ W1 + b1); 2 passes x 8 tiles per warp ---
    {
        int rowg = w & 7, ch = w >> 3;   // ch in {0,1}: warp covers 128 cols
        #pragma unroll
        for (int pass = 0; pass < 2; pass++) {
            float acc[8][4];
            #pragma unroll
            for (int tt = 0; tt < 8; tt++) {
                int n0 = (ch * 16 + pass * 8 + tt) * 8;
                float v0 = __ldg(b1 + n0 + 2 * tg), v1 = __ldg(b1 + n0 + 2 * tg + 1);
                acc[tt][0] = v0; acc[tt][1] = v1; acc[tt][2] = v0; acc[tt][3] = v1;
            }
            #pragma unroll
            for (int ks = 0; ks < 4; ks++) {
                unsigned a[4];
                *(uint4*)a = *(const uint4*)&sXp[((rowg * 4 + ks) * 32 + lane) * 4];
                #pragma unroll
                for (int tp = 0; tp < 4; tp++) {
                    unsigned bb[4];
                    *(uint4*)bb = *(const uint4*)
                        &sWp[((ks * 16 + ch * 8 + pass * 4 + tp) * 32 + lane) * 4];
                    mma16(acc[2 * tp],     a, bb);
                    mma16(acc[2 * tp + 1], a, bb + 2);
                }
            }
            // relu + pack 4 values into 2 half2 words, one STS.64 per tile
            #pragma unroll
            for (int tt = 0; tt < 8; tt++) {
                int tile = ch * 16 + pass * 8 + tt;
                int kstepB = tile >> 1, hkB = tile & 1;
                unsigned w0 = pack2(fmaxf(acc[tt][0], 0.f), fmaxf(acc[tt][1], 0.f));
                unsigned w1 = pack2(fmaxf(acc[tt][2], 0.f), fmaxf(acc[tt][3], 0.f));
                int base = ((rowg * 16 + kstepB) * 32 + g * 4 + tg) * 4 + 2 * hkB;
                *(uint2*)&sHp[base] = make_uint2(w0, w1);
            }
        }
    }
    __syncthreads();

    // --- zero stats partials, W2 permute-load [256][64] (packed) ---
    if (t < 128) sS[t] = 0.f;
    #pragma unroll
    for (int i = 0; i < (HID / 2 * OUTD) / 512; i++) {  // 16 iters
        int idx = i * 512 + t;
        int kp = idx >> 6, o = idx & 63, k0 = kp * 2;
        float w0 = W2[k0 * OUTD + o], w1 = W2[(k0 + 1) * OUTD + o];
        int kstep = k0 >> 4, kk = k0 & 15, tt = (kk & 7) >> 1, breg = kk >> 3;
        int tile = o >> 3, gg = o & 7;
        sWp[((kstep * 4 + (tile >> 1)) * 32 + gg * 4 + tt) * 4 + (tile & 1) * 2 + breg]
            = pack2(w0, w1);
    }
    __syncthreads();

    // --- Phase B: y = relu(H @ W2 + b2), write y + BN partials ---
    {
        int rowg = w & 7, ch = w >> 3;   // ch in {0,1}: 4 n-tiles each
        float acc[4][4];
        #pragma unroll
        for (int tt = 0; tt < 4; tt++) {
            int o0 = (ch * 4 + tt) * 8;
            float v0 = __ldg(b2 + o0 + 2 * tg), v1 = __ldg(b2 + o0 + 2 * tg + 1);
            acc[tt][0] = v0; acc[tt][1] = v1; acc[tt][2] = v0; acc[tt][3] = v1;
        }
        #pragma unroll
        for (int ks = 0; ks < 16; ks++) {
            unsigned a[4];
            *(uint4*)a = *(const uint4*)&sHp[((rowg * 16 + ks) * 32 + lane) * 4];
            #pragma unroll
            for (int tp = 0; tp < 2; tp++) {
                unsigned bb[4];
                *(uint4*)bb = *(const uint4*)
                    &sWp[((ks * 4 + ch * 2 + tp) * 32 + lane) * 4];
                mma16(acc[2 * tp],     a, bb);
                mma16(acc[2 * tp + 1], a, bb + 2);
            }
        }
        float ps[8] = {0,0,0,0,0,0,0,0}, pq[8] = {0,0,0,0,0,0,0,0};
        #pragma unroll
        for (int tt = 0; tt < 4; tt++) {
            #pragma unroll
            for (int cr = 0; cr < 4; cr++) {
                int row = nb + rowg * 16 + g + (cr >> 1) * 8;
                int col = (ch * 4 + tt) * 8 + 2 * tg + (cr & 1);
                float y = fmaxf(acc[tt][cr], 0.f);
                if (row < N_NODES) {
                    g_y[(size_t)row * OUTD + col] = y;
                    ps[tt * 2 + (cr & 1)] += y;
                    pq[tt * 2 + (cr & 1)] += y * y;
                }
            }
        }
        #pragma unroll
        for (int i = 0; i < 8; i++) {
            int col = (ch * 4 + (i >> 1)) * 8 + 2 * tg + (i & 1);
            atomicAdd(&sS[col], ps[i]);
            atomicAdd(&sS[64 + col], pq[i]);
        }
    }
    __syncthreads();
    if (t < 128) {
        atomicAdd(&g_stats[t], sS[t]);
        __threadfence();
    }
    __syncthreads();
    if (t == 0)
        s_last = (atomicAdd(&g_done, 1u) == (unsigned)(gridDim.x - 1)) ? 1 : 0;
    __syncthreads();
    if (s_last) {
        __threadfence();
        if (t < OUTD) {
            float s0 = atomicAdd(&g_stats[t], 0.f);
            float q  = atomicAdd(&g_stats[OUTD + t], 0.f);
            float mean = s0 * (1.0f / N_NODES);
            float var = q * (1.0f / N_NODES) - mean * mean;
            float sc = gamma[t] * rsqrtf(var + BN_EPS);
            g_scale[t] = sc;
            g_shift[t] = beta[t] - mean * sc;
        }
        __syncthreads();
        if (t < 2 * OUTD) g_stats[t] = 0.f;
        if (t == 0) g_done = 0;
    }
}

// -------------------------------------------------------------------
__global__ void k_apply(float* __restrict__ out) {
    int i = blockIdx.x * blockDim.x + threadIdx.x;
    if (i >= N_NODES * OUTD / 4) return;
    int o4 = (i & (OUTD / 4 - 1)) * 4;
    float4 y = ((const float4*)g_y)[i];
    float4 r;
    r.x = y.x * g_scale[o4 + 0] + g_shift[o4 + 0];
    r.y = y.y * g_scale[o4 + 1] + g_shift[o4 + 1];
    r.z = y.z * g_scale[o4 + 2] + g_shift[o4 + 2];
    r.w = y.w * g_scale[o4 + 3] + g_shift[o4 + 3];
    ((float4*)out)[i] = r;
}

// -------------------------------------------------------------------
extern "C" void kernel_launch(void* const* d_in, const int* in_sizes, int n_in,
                              void* d_out, int out_size) {
    const float* h     = (const float*)d_in[0];
    const float* W1    = (const float*)d_in[1];
    const float* b1    = (const float*)d_in[2];
    const float* W2    = (const float*)d_in[3];
    const float* b2    = (const float*)d_in[4];
    const float* gamma = (const float*)d_in[5];
    const float* beta  = (const float*)d_in[6];
    const int*   src   = (const int*)d_in[7];
    const int*   dst   = (const int*)d_in[8];
    float* out = (float*)d_out;

    const int smem_bytes = (4096 + 16384 + 8192) * 4;  // 114688
    cudaFuncSetAttribute(k_mlp, cudaFuncAttributeMaxDynamicSharedMemorySize, smem_bytes);

    k_count<<<N_EDGES / 256, 256>>>(dst);
    k_scan<<<NBLK, 256>>>();
    k_fill<<<N_EDGES / 256, 256>>>(src, dst);
    k_gather<<<(N_NODES * 32 + 255) / 256, 256>>>(h);
    k_mlp<<<(N_NODES + MB - 1) / MB, 512, smem_bytes>>>(h, W1, b1, W2, b2, gamma, beta);
    k_apply<<<(N_NODES * OUTD / 4 + 255) / 256, 256>>>(out);
}

// round 14
// speedup vs baseline: 1.3543x; 1.1500x over previous
#include <cuda_runtime.h>
#include <cuda_fp16.h>

#define N_NODES 100000
#define N_EDGES 1600000
#define D 64
#define HID 256
#define OUTD 64
#define MB 128           // nodes per MLP CTA
#define BN_EPS 1e-5f
#define NBLK 391         // ceil(N_NODES/256)

// ---- device scratch (no allocations allowed; zero-initialized at load) ----
__device__ float g_agg[N_NODES * D];
__device__ int   g_cnt[N_NODES];              // in-degree (re-zeroed by k_mlp)
__device__ int   g_off[N_NODES];              // CSR offsets
__device__ int   g_pos[N_NODES];              // fill cursors
__device__ unsigned long long g_desc[NBLK];   // scan descriptors (reset in k_build)
__device__ int   g_csr[N_EDGES];              // src ids grouped by dst
__device__ float g_y[N_NODES * OUTD];
__device__ float g_stats[2 * OUTD];           // re-zeroed by k_mlp last CTA
__device__ float g_scale[OUTD];
__device__ float g_shift[OUTD];
__device__ unsigned g_done;                   // re-zeroed by k_mlp last CTA
__device__ unsigned g_arr1, g_arr2;           // k_build grid barrier (self-resetting)

// -------------------------------------------------------------------
// k_build: count in-degrees (strided) -> grid barrier -> lookback scan.
// All 391 CTAs are co-resident (391 << 148*CTAs/SM) so spinning is safe.
// -------------------------------------------------------------------
__global__ void k_build(const int* __restrict__ dst) {
    __shared__ int s[256];
    __shared__ int s_excl;
    int b = blockIdx.x, t = threadIdx.x;
    int gid = b * 256 + t;

    // reset scan descriptors for this replay (before the barrier)
    if (gid < NBLK) g_desc[gid] = 0ULL;

    // strided count: 391*256 = 100096 threads, 16 iters
    for (int e = gid; e < N_EDGES; e += NBLK * 256)
        atomicAdd(&g_cnt[__ldg(dst + e)], 1);
    __threadfence();
    __syncthreads();

    // grid-wide barrier (arrive + spin); counters reset at kernel end
    if (t == 0) {
        atomicAdd(&g_arr1, 1u);
        while (atomicAdd(&g_arr1, 0u) < (unsigned)NBLK) { }
    }
    __syncthreads();
    __threadfence();

    // block-local inclusive scan of g_cnt slice
    int i = gid;
    int v = (i < N_NODES) ? g_cnt[i] : 0;
    s[t] = v; __syncthreads();
    #pragma unroll
    for (int off = 1; off < 256; off <<= 1) {
        int x = (t >= off) ? s[t - off] : 0;
        __syncthreads();
        s[t] += x;
        __syncthreads();
    }
    int total = s[255];

    // decoupled lookback across blocks
    if (t == 0) {
        unsigned long long flag = (b == 0) ? 2ULL : 1ULL;
        atomicExch(&g_desc[b], (flag << 62) | (unsigned)total);
        int excl = 0;
        if (b > 0) {
            int ib = b - 1;
            while (true) {
                unsigned long long d;
                do { d = atomicAdd(&g_desc[ib], 0ULL); } while ((d >> 62) == 0ULL);
                excl += (int)(d & 0xffffffffULL);
                if ((d >> 62) == 2ULL) break;
                ib--;
            }
            atomicExch(&g_desc[b], (2ULL << 62) | (unsigned)(excl + total));
        }
        s_excl = excl;
    }
    __syncthreads();
    if (i < N_NODES) {
        int o = s_excl + s[t] - v;
        g_off[i] = o;
        g_pos[i] = o;
    }

    // reset barrier counters for next replay (safe: everyone passed barrier 1)
    if (t == 0) {
        unsigned a2 = atomicAdd(&g_arr2, 1u);
        if (a2 == (unsigned)(NBLK - 1)) { g_arr1 = 0; g_arr2 = 0; }
    }
}

// -------------------------------------------------------------------
__global__ void k_fill(const int* __restrict__ src, const int* __restrict__ dst) {
    int e = blockIdx.x * blockDim.x + threadIdx.x;
    if (e < N_EDGES) {
        int d = __ldg(dst + e);
        int p = atomicAdd(&g_pos[d], 1);
        g_csr[p] = __ldg(src + e);
    }
}

// -------------------------------------------------------------------
// Atomic-free gather: one warp per node; 8 independent row reads in flight.
// -------------------------------------------------------------------
__global__ void k_gather(const float* __restrict__ h) {
    int w = (blockIdx.x * blockDim.x + threadIdx.x) >> 5;
    if (w >= N_NODES) return;
    int lane = threadIdx.x & 31;
    int beg = g_off[w], cnt = g_cnt[w];
    float ax = 0.f, ay = 0.f;
    int j = 0;
    for (; j + 8 <= cnt; j += 8) {
        int sidx[8];
        #pragma unroll
        for (int u = 0; u < 8; u++) sidx[u] = __ldg(g_csr + beg + j + u);
        #pragma unroll
        for (int u = 0; u < 8; u++) {
            float2 v = *(const float2*)(h + (size_t)sidx[u] * D + lane * 2);
            ax += v.x; ay += v.y;
        }
    }
    for (; j < cnt; j++) {
        int s0 = __ldg(g_csr + beg + j);
        float2 v = *(const float2*)(h + (size_t)s0 * D + lane * 2);
        ax += v.x; ay += v.y;
    }
    *(float2*)(g_agg + (size_t)w * D + lane * 2) = make_float2(ax, ay);
}

// -------------------------------------------------------------------
// fp16 mma helpers (m16n8k16, fp32 accumulate)
// -------------------------------------------------------------------
__device__ __forceinline__ unsigned pack2(float a, float b) {
    __half2 hh = __halves2half2(__float2half_rn(a), __float2half_rn(b));
    return *(unsigned*)&hh;
}
__device__ __forceinline__ void mma16(float* c, const unsigned* a, const unsigned* b) {
    asm volatile(
        "mma.sync.aligned.m16n8k16.row.col.f32.f16.f16.f32 "
        "{%0,%1,%2,%3},{%4,%5,%6,%7},{%8,%9},{%0,%1,%2,%3};"
        : "+f"(c[0]), "+f"(c[1]), "+f"(c[2]), "+f"(c[3])
        : "r"(a[0]), "r"(a[1]), "r"(a[2]), "r"(a[3]), "r"(b[0]), "r"(b[1]));
}

// -------------------------------------------------------------------
// Fused MLP (fp16 m16n8k16), 512 threads / 16 warps, 2 CTAs/SM.
// smem 114688 B -> two CTAs fit in the 228KB carveout; launch_bounds
// caps regs at 64/thread so both CTAs are resident (32 warps/SM).
// -------------------------------------------------------------------
__global__ __launch_bounds__(512, 2)
void k_mlp(const float* __restrict__ h,
           const float* __restrict__ W1, const float* __restrict__ b1,
           const float* __restrict__ W2, const float* __restrict__ b2,
           const float* __restrict__ gamma, const float* __restrict__ beta) {
    extern __shared__ unsigned smu[];
    unsigned* sXp = smu;                    // 4096 words
    unsigned* sHp = smu + 4096;             // 16384 words
    unsigned* sWp = smu + 4096 + 16384;     // 8192 words
    float* sS = (float*)smu;                // stats reuse (phase B; sXp dead then)
    __shared__ float sInv[MB];
    __shared__ int s_last;

    int t = threadIdx.x;
    int lane = t & 31, w = t >> 5;
    int g = lane >> 2, tg = lane & 3;
    int nb = blockIdx.x * MB;

    // --- per-row 1/deg, consume + zero g_cnt ---
    if (t < MB) {
        int gn = nb + t;
        float invd = 0.f;
        if (gn < N_NODES) {
            float dg = (float)g_cnt[gn];
            invd = 1.f / fmaxf(dg, 1.f);
            g_cnt[gn] = 0;
        }
        sInv[t] = invd;
    }
    __syncthreads();

    // --- X permute-load (packed pairs): x = agg*invdeg + h ---
    #pragma unroll
    for (int i = 0; i < (MB * D / 2) / 512; i++) {   // 8 iters
        int idx = i * 512 + t;
        int row = idx >> 5, kp = idx & 31, k0 = kp * 2;
        int gn = nb + row;
        float x0 = 0.f, x1 = 0.f;
        if (gn < N_NODES) {
            float2 av = *(const float2*)(g_agg + (size_t)gn * D + k0);
            float2 hv = *(const float2*)(h + (size_t)gn * D + k0);
            float iv = sInv[row];
            x0 = av.x * iv + hv.x;
            x1 = av.y * iv + hv.y;
        }
        int rowg = row >> 4, r = row & 15, gg = r & 7, hr = r >> 3;
        int kstep = k0 >> 4, kk = k0 & 15, tt = (kk & 7) >> 1, hk = kk >> 3;
        sXp[((rowg * 4 + kstep) * 32 + gg * 4 + tt) * 4 + hr + 2 * hk] = pack2(x0, x1);
    }
    // --- W1 permute-load [64][256] (pack along k, tile-paired) ---
    #pragma unroll
    for (int i = 0; i < (D / 2 * HID) / 512; i++) {  // 16 iters
        int idx = i * 512 + t;
        int kp = idx >> 8, n = idx & 255, k0 = kp * 2;
        float w0 = W1[k0 * HID + n], w1 = W1[(k0 + 1) * HID + n];
        int kstep = k0 >> 4, kk = k0 & 15, tt = (kk & 7) >> 1, breg = kk >> 3;
        int tile = n >> 3, gg = n & 7;
        sWp[((kstep * 16 + (tile >> 1)) * 32 + gg * 4 + tt) * 4 + (tile & 1) * 2 + breg]
            = pack2(w0, w1);
    }
    __syncthreads();

    // --- Phase A: H = relu(X @ W1 + b1); 2 passes x 8 tiles per warp ---
    {
        int rowg = w & 7, ch = w >> 3;
        #pragma unroll
        for (int pass = 0; pass < 2; pass++) {
            float acc[8][4];
            #pragma unroll
            for (int tt = 0; tt < 8; tt++) {
                int n0 = (ch * 16 + pass * 8 + tt) * 8;
                float v0 = __ldg(b1 + n0 + 2 * tg), v1 = __ldg(b1 + n0 + 2 * tg + 1);
                acc[tt][0] = v0; acc[tt][1] = v1; acc[tt][2] = v0; acc[tt][3] = v1;
            }
            #pragma unroll
            for (int ks = 0; ks < 4; ks++) {
                unsigned a[4];
                *(uint4*)a = *(const uint4*)&sXp[((rowg * 4 + ks) * 32 + lane) * 4];
                #pragma unroll
                for (int tp = 0; tp < 4; tp++) {
                    unsigned bb[4];
                    *(uint4*)bb = *(const uint4*)
                        &sWp[((ks * 16 + ch * 8 + pass * 4 + tp) * 32 + lane) * 4];
                    mma16(acc[2 * tp],     a, bb);
                    mma16(acc[2 * tp + 1], a, bb + 2);
                }
            }
            #pragma unroll
            for (int tt = 0; tt < 8; tt++) {
                int tile = ch * 16 + pass * 8 + tt;
                int kstepB = tile >> 1, hkB = tile & 1;
                unsigned w0 = pack2(fmaxf(acc[tt][0], 0.f), fmaxf(acc[tt][1], 0.f));
                unsigned w1 = pack2(fmaxf(acc[tt][2], 0.f), fmaxf(acc[tt][3], 0.f));
                int base = ((rowg * 16 + kstepB) * 32 + g * 4 + tg) * 4 + 2 * hkB;
                *(uint2*)&sHp[base] = make_uint2(w0, w1);
            }
        }
    }
    __syncthreads();

    // --- zero stats partials, W2 permute-load [256][64] (packed) ---
    if (t < 128) sS[t] = 0.f;
    #pragma unroll
    for (int i = 0; i < (HID / 2 * OUTD) / 512; i++) {  // 16 iters
        int idx = i * 512 + t;
        int kp = idx >> 6, o = idx & 63, k0 = kp * 2;
        float w0 = W2[k0 * OUTD + o], w1 = W2[(k0 + 1) * OUTD + o];
        int kstep = k0 >> 4, kk = k0 & 15, tt = (kk & 7) >> 1, breg = kk >> 3;
        int tile = o >> 3, gg = o & 7;
        sWp[((kstep * 4 + (tile >> 1)) * 32 + gg * 4 + tt) * 4 + (tile & 1) * 2 + breg]
            = pack2(w0, w1);
    }
    __syncthreads();

    // --- Phase B: y = relu(H @ W2 + b2), write y + BN partials ---
    {
        int rowg = w & 7, ch = w >> 3;
        float acc[4][4];
        #pragma unroll
        for (int tt = 0; tt < 4; tt++) {
            int o0 = (ch * 4 + tt) * 8;
            float v0 = __ldg(b2 + o0 + 2 * tg), v1 = __ldg(b2 + o0 + 2 * tg + 1);
            acc[tt][0] = v0; acc[tt][1] = v1; acc[tt][2] = v0; acc[tt][3] = v1;
        }
        #pragma unroll
        for (int ks = 0; ks < 16; ks++) {
            unsigned a[4];
            *(uint4*)a = *(const uint4*)&sHp[((rowg * 16 + ks) * 32 + lane) * 4];
            #pragma unroll
            for (int tp = 0; tp < 2; tp++) {
                unsigned bb[4];
                *(uint4*)bb = *(const uint4*)
                    &sWp[((ks * 4 + ch * 2 + tp) * 32 + lane) * 4];
                mma16(acc[2 * tp],     a, bb);
                mma16(acc[2 * tp + 1], a, bb + 2);
            }
        }
        float ps[8] = {0,0,0,0,0,0,0,0}, pq[8] = {0,0,0,0,0,0,0,0};
        #pragma unroll
        for (int tt = 0; tt < 4; tt++) {
            #pragma unroll
            for (int cr = 0; cr < 4; cr++) {
                int row = nb + rowg * 16 + g + (cr >> 1) * 8;
                int col = (ch * 4 + tt) * 8 + 2 * tg + (cr & 1);
                float y = fmaxf(acc[tt][cr], 0.f);
                if (row < N_NODES) {
                    g_y[(size_t)row * OUTD + col] = y;
                    ps[tt * 2 + (cr & 1)] += y;
                    pq[tt * 2 + (cr & 1)] += y * y;
                }
            }
        }
        #pragma unroll
        for (int i = 0; i < 8; i++) {
            int col = (ch * 4 + (i >> 1)) * 8 + 2 * tg + (i & 1);
            atomicAdd(&sS[col], ps[i]);
            atomicAdd(&sS[64 + col], pq[i]);
        }
    }
    __syncthreads();
    if (t < 128) {
        atomicAdd(&g_stats[t], sS[t]);
        __threadfence();
    }
    __syncthreads();
    if (t == 0)
        s_last = (atomicAdd(&g_done, 1u) == (unsigned)(gridDim.x - 1)) ? 1 : 0;
    __syncthreads();
    if (s_last) {
        __threadfence();
        if (t < OUTD) {
            float s0 = atomicAdd(&g_stats[t], 0.f);
            float q  = atomicAdd(&g_stats[OUTD + t], 0.f);
            float mean = s0 * (1.0f / N_NODES);
            float var = q * (1.0f / N_NODES) - mean * mean;
            float sc = gamma[t] * rsqrtf(var + BN_EPS);
            g_scale[t] = sc;
            g_shift[t] = beta[t] - mean * sc;
        }
        __syncthreads();
        if (t < 2 * OUTD) g_stats[t] = 0.f;
        if (t == 0) g_done = 0;
    }
}

// -------------------------------------------------------------------
__global__ void k_apply(float* __restrict__ out) {
    int i = blockIdx.x * blockDim.x + threadIdx.x;
    if (i >= N_NODES * OUTD / 4) return;
    int o4 = (i & (OUTD / 4 - 1)) * 4;
    float4 y = ((const float4*)g_y)[i];
    float4 r;
    r.x = y.x * g_scale[o4 + 0] + g_shift[o4 + 0];
    r.y = y.y * g_scale[o4 + 1] + g_shift[o4 + 1];
    r.z = y.z * g_scale[o4 + 2] + g_shift[o4 + 2];
    r.w = y.w * g_scale[o4 + 3] + g_shift[o4 + 3];
    ((float4*)out)[i] = r;
}

// -------------------------------------------------------------------
extern "C" void kernel_launch(void* const* d_in, const int* in_sizes, int n_in,
                              void* d_out, int out_size) {
    const float* h     = (const float*)d_in[0];
    const float* W1    = (const float*)d_in[1];
    const float* b1    = (const float*)d_in[2];
    const float* W2    = (const float*)d_in[3];
    const float* b2    = (const float*)d_in[4];
    const float* gamma = (const float*)d_in[5];
    const float* beta  = (const float*)d_in[6];
    const int*   src   = (const int*)d_in[7];
    const int*   dst   = (const int*)d_in[8];
    float* out = (float*)d_out;

    const int smem_bytes = (4096 + 16384 + 8192) * 4;  // 114688
    cudaFuncSetAttribute(k_mlp, cudaFuncAttributeMaxDynamicSharedMemorySize, smem_bytes);

    k_build<<<NBLK, 256>>>(dst);
    k_fill<<<N_EDGES / 256, 256>>>(src, dst);
    k_gather<<<(N_NODES * 32 + 255) / 256, 256>>>(h);
    k_mlp<<<(N_NODES + MB - 1) / MB, 512, smem_bytes>>>(h, W1, b1, W2, b2, gamma, beta);  // slot 4 -> profiled
    k_apply<<<(N_NODES * OUTD / 4 + 255) / 256, 256>>>(out);
}